// round 10
// baseline (speedup 1.0000x reference)
#include <cuda_runtime.h>
#include <math.h>
#include <stdint.h>

#define SQn   2048
#define SKn   64
#define Cn    256
#define HWn   256
#define En    512
#define NPn   (SQn*SKn)
#define NHn   8
#define HDn   64

typedef unsigned long long u64;

__device__ __forceinline__ u64 fma2(u64 a, u64 b, u64 c) {
    u64 d;
    asm("fma.rn.f32x2 %0, %1, %2, %3;" : "=l"(d) : "l"(a), "l"(b), "l"(c));
    return d;
}
__device__ __forceinline__ u64 pack2(float lo, float hi) {
    u64 v;
    asm("mov.b64 %0, {%1, %2};" : "=l"(v) : "f"(lo), "f"(hi));
    return v;
}
__device__ __forceinline__ float2 unpack2(u64 v) {
    float lo, hi;
    asm("mov.b64 {%0, %1}, %2;" : "=f"(lo), "=f"(hi) : "l"(v));
    return make_float2(lo, hi);
}
__device__ __forceinline__ u64 splat2(float a) { return pack2(a, a); }

__device__ __forceinline__ uint32_t f2tf(float f) {
    uint32_t u;
    asm("cvt.rna.tf32.f32 %0, %1;" : "=r"(u) : "f"(f));
    return u;
}
__device__ __forceinline__ uint4 cvt4(float4 v) {
    return make_uint4(f2tf(v.x), f2tf(v.y), f2tf(v.z), f2tf(v.w));
}
__device__ __forceinline__ void mma_tf32(float& d0, float& d1, float& d2, float& d3,
                                         uint32_t a0, uint32_t a1, uint32_t a2, uint32_t a3,
                                         uint32_t b0, uint32_t b1) {
    asm volatile(
        "mma.sync.aligned.m16n8k8.row.col.f32.tf32.tf32.f32 "
        "{%0,%1,%2,%3}, {%4,%5,%6,%7}, {%8,%9}, {%0,%1,%2,%3};"
        : "+f"(d0), "+f"(d1), "+f"(d2), "+f"(d3)
        : "r"(a0), "r"(a1), "r"(a2), "r"(a3), "r"(b0), "r"(b1));
}

// ---------------- scratch ----------------
__device__ float g_Zt[(size_t)Cn*HWn*HWn];      // 67 MB   Zt[x][y][c]
__device__ float g_key2[(size_t)NPn*256];       // 134 MB  interp half of key
__device__ float g_ql[(size_t)SQn*En];
__device__ float g_qk[(size_t)SQn*NHn*En];
__device__ float g_ctx[(size_t)SQn*NHn*En];
__device__ float g_out1[(size_t)SQn*En];

// ---------------- 1) transpose Z (C, HW*HW) -> Zt (HW*HW, C) ----------------
__global__ void transpose_kernel(const float* __restrict__ Z) {
    __shared__ float tile[32][33];
    int xy0 = blockIdx.x * 32;
    int c0  = blockIdx.y * 32;
    int tx = threadIdx.x, ty = threadIdx.y;   // 32 x 8
    #pragma unroll
    for (int i = 0; i < 32; i += 8)
        tile[ty + i][tx] = Z[(long)(c0 + ty + i) * (HWn*HWn) + xy0 + tx];
    __syncthreads();
    #pragma unroll
    for (int i = 0; i < 32; i += 8)
        g_Zt[(long)(xy0 + ty + i) * Cn + c0 + tx] = tile[tx][ty + i];
}

// ================= tf32 mma compute core (shared logic, macro-free duplication) =================
// smem: As[128][20] m-major tf32 bits, Bs[64][20] n-major tf32 bits. 256 thr = 8 warps.
// warp w: wm = w&3 (m-offset wm*32), wn = w>>2 (n-offset wn*32). lane: g = l>>2, q = l&3.
// Per 16-k chunk: 2 k8 steps; per step: A frags (2 msub), B frags (4 nsub), 8 mma.

#define GEMM_AS_SZ (128*20)
#define GEMM_BS_SZ (64*20)

// ---------------- 2) FAT kernel: gemm1(query fused, tf32) | qz->out copy | interp ----------------
#define FAT_GEMM_BLKS 128
#define FAT_COPY_BLKS 16
#define FAT_INTERP_OFF (FAT_GEMM_BLKS + FAT_COPY_BLKS)

struct InterpS { float sres[256][33]; int soff[32]; float sdx[32], sdy[32]; };
struct GemmS   { uint32_t As[GEMM_AS_SZ]; uint32_t Bs[GEMM_BS_SZ]; };

__global__ __launch_bounds__(256)
void fat_kernel(const float* __restrict__ r,
                const float* __restrict__ q_z,
                const float* __restrict__ Q,
                const float* __restrict__ w2,
                const float* __restrict__ b2,
                const float* __restrict__ in_proj_w,
                const float* __restrict__ in_proj_b,
                float* __restrict__ outp) {
    __shared__ __align__(16) char smraw[sizeof(InterpS)];
    int bx = blockIdx.x;
    int t = threadIdx.x;

    if (bx < FAT_GEMM_BLKS) {
        // ---------- gemm1 (tf32) with fused query A ----------
        GemmS* S = (GemmS*)smraw;
        int m0 = (bx >> 3) * 128;
        int n0 = (bx & 7) * 64;
        int ar = t >> 2, ac = (t & 3) * 4;
        int w = t >> 5, l = t & 31;
        int wm = w & 3, wn = w >> 2;
        int g = l >> 2, q = l & 3;

        int rowA = m0 + ar, rowB = m0 + ar + 64;
        float qa0 = Q[rowA*3+0], qa1 = Q[rowA*3+1], qa2 = Q[rowA*3+2];
        float qb0 = Q[rowB*3+0], qb1 = Q[rowB*3+1], qb2 = Q[rowB*3+2];

        auto loadA = [&](int row, float q0, float q1, float q2, int k)->float4 {
            if (k < 256) {
                return *(const float4*)(q_z + (long)row*256 + k);
            } else {
                int h = k - 256;
                const float* w2r = w2 + h*3;
                float4 v;
                v.x = q0*w2r[0] + q1*w2r[1]  + q2*w2r[2]  + b2[h+0];
                v.y = q0*w2r[3] + q1*w2r[4]  + q2*w2r[5]  + b2[h+1];
                v.z = q0*w2r[6] + q1*w2r[7]  + q2*w2r[8]  + b2[h+2];
                v.w = q0*w2r[9] + q1*w2r[10] + q2*w2r[11] + b2[h+3];
                return v;
            }
        };

        uint4 ua0 = cvt4(loadA(rowA, qa0, qa1, qa2, ac));
        uint4 ua1 = cvt4(loadA(rowB, qb0, qb1, qb2, ac));
        uint4 ub  = cvt4(*(const float4*)(in_proj_w + (long)(n0 + ar) * En + ac));

        float acc[2][4][4] = {};
        for (int k0 = 0; k0 < En; k0 += 16) {
            *(uint4*)(&S->As[(ar     )*20 + ac]) = ua0;
            *(uint4*)(&S->As[(ar + 64)*20 + ac]) = ua1;
            *(uint4*)(&S->Bs[(ar     )*20 + ac]) = ub;
            __syncthreads();
            if (k0 + 16 < En) {
                ua0 = cvt4(loadA(rowA, qa0, qa1, qa2, k0 + 16 + ac));
                ua1 = cvt4(loadA(rowB, qb0, qb1, qb2, k0 + 16 + ac));
                ub  = cvt4(*(const float4*)(in_proj_w + (long)(n0 + ar) * En + k0 + 16 + ac));
            }
            #pragma unroll
            for (int ks = 0; ks < 2; ks++) {
                int kk = ks * 8;
                uint32_t af[2][4];
                #pragma unroll
                for (int ms = 0; ms < 2; ms++) {
                    int mr = wm*32 + ms*16 + g;
                    af[ms][0] = S->As[(mr    )*20 + kk + q];
                    af[ms][1] = S->As[(mr + 8)*20 + kk + q];
                    af[ms][2] = S->As[(mr    )*20 + kk + q + 4];
                    af[ms][3] = S->As[(mr + 8)*20 + kk + q + 4];
                }
                uint32_t bf[4][2];
                #pragma unroll
                for (int ns = 0; ns < 4; ns++) {
                    int nc = wn*32 + ns*8 + g;
                    bf[ns][0] = S->Bs[nc*20 + kk + q];
                    bf[ns][1] = S->Bs[nc*20 + kk + q + 4];
                }
                #pragma unroll
                for (int ms = 0; ms < 2; ms++)
                    #pragma unroll
                    for (int ns = 0; ns < 4; ns++)
                        mma_tf32(acc[ms][ns][0], acc[ms][ns][1], acc[ms][ns][2], acc[ms][ns][3],
                                 af[ms][0], af[ms][1], af[ms][2], af[ms][3],
                                 bf[ns][0], bf[ns][1]);
            }
            __syncthreads();
        }
        #pragma unroll
        for (int ms = 0; ms < 2; ms++)
            #pragma unroll
            for (int ns = 0; ns < 4; ns++) {
                int row0 = m0 + wm*32 + ms*16 + g;
                int col  = n0 + wn*32 + ns*8 + 2*q;
                float bx0 = in_proj_b[col], bx1 = in_proj_b[col+1];
                *(float2*)(&g_ql[(long)row0*En + col]) =
                    make_float2(acc[ms][ns][0] + bx0, acc[ms][ns][1] + bx1);
                *(float2*)(&g_ql[(long)(row0+8)*En + col]) =
                    make_float2(acc[ms][ns][2] + bx0, acc[ms][ns][3] + bx1);
            }
    } else if (bx < FAT_INTERP_OFF) {
        // ---------- q_z -> outp[:, 0:256) ----------
        int r0 = (bx - FAT_GEMM_BLKS) * 128;
        #pragma unroll
        for (int i = 0; i < 32; i++) {
            int idx = i * 256 + t;
            int row = r0 + (idx >> 6);
            int c4  = (idx & 63) * 4;
            float4 v = *(const float4*)(q_z + (long)row*256 + c4);
            *(float4*)(outp + (long)row*768 + c4) = v;
        }
    } else {
        // ---------- bilinear interp ----------
        InterpS* S = (InterpS*)smraw;
        int p0 = (bx - FAT_INTERP_OFF) * 32;
        if (t < 32) {
            float x = r[2*(p0+t)], y = r[2*(p0+t)+1];
            int x1 = (int)x, y1 = (int)y;
            S->soff[t] = (x1*HWn + y1)*Cn;
            S->sdx[t] = x - (float)x1;
            S->sdy[t] = y - (float)y1;
        }
        __syncthreads();
        int wp = t >> 5, l = t & 31;
        #pragma unroll
        for (int pi = 0; pi < 4; pi++) {
            int pl = wp*4 + pi;
            long off = S->soff[pl];
            float dx = S->sdx[pl], dy = S->sdy[pl];
            float omdx = 1.0f - dx, omdy = 1.0f - dy;
            #pragma unroll
            for (int rep = 0; rep < 2; rep++) {
                int c = rep*128 + l*4;
                const float* z11 = g_Zt + off + c;
                float4 a  = *(const float4*)(z11);
                float4 cq = *(const float4*)(z11 + Cn);
                float4 b  = *(const float4*)(z11 + HWn*Cn);
                float4 d  = *(const float4*)(z11 + HWn*Cn + Cn);
                S->sres[c+0][pl] = (a.x*omdx + b.x*dx)*omdy + (cq.x*omdx + d.x*dx)*dy;
                S->sres[c+1][pl] = (a.y*omdx + b.y*dx)*omdy + (cq.y*omdx + d.y*dx)*dy;
                S->sres[c+2][pl] = (a.z*omdx + b.z*dx)*omdy + (cq.z*omdx + d.z*dx)*dy;
                S->sres[c+3][pl] = (a.w*omdx + b.w*dx)*omdy + (cq.w*omdx + d.w*dx)*dy;
            }
        }
        __syncthreads();
        long rowhi = (long)(p0 >> 8);
        int  colb  = p0 & 255;
        #pragma unroll
        for (int i = 0; i < 32; i++) {
            int c = wp*32 + i;
            g_key2[((long)c*512 + rowhi)*256 + colb + l] = S->sres[c][l];
        }
    }
}

// ---------------- generic tf32 GEMM: 128x64 tile, 256 thr ----------------
// C[m][n] = sum_k A[m*lda+k] * B[n*ldbn + k*ldbk] + bias[n]
__global__ __launch_bounds__(256)
void gemm_kernel(const float* __restrict__ A, int lda, long sA,
                 const float* __restrict__ B, int ldbn, int ldbk, long sB,
                 float* __restrict__ Cp, int ldc, long sC,
                 const float* __restrict__ bias, long sBias,
                 int M, int N, int K) {
    int batch = blockIdx.z;
    A  += (long)batch * sA;
    B  += (long)batch * sB;
    Cp += (long)batch * sC;
    if (bias) bias += (long)batch * sBias;

    __shared__ uint32_t As[GEMM_AS_SZ];
    __shared__ uint32_t Bs[GEMM_BS_SZ];
    int t = threadIdx.x;
    int m0 = blockIdx.y * 128, n0 = blockIdx.x * 64;
    int ar = t >> 2, ac = (t & 3) * 4;
    int w = t >> 5, l = t & 31;
    int wm = w & 3, wn = w >> 2;
    int g = l >> 2, q = l & 3;

    const bool bvec = (ldbk == 1);
    const float* Abase = A + (long)(m0 + ar) * lda + ac;

    uint4 ua0 = cvt4(*(const float4*)(Abase));
    uint4 ua1 = cvt4(*(const float4*)(Abase + (long)64 * lda));
    uint4 ub;
    uint32_t ubs[4];
    if (bvec) {
        ub = cvt4(*(const float4*)(B + (long)(n0 + ar) * ldbn + ac));
    } else {
        #pragma unroll
        for (int p = 0; p < 4; p++) {
            int idx = t + 256*p; int nn = idx & 63, kk = idx >> 6;
            ubs[p] = f2tf(B[(long)(n0 + nn) + (long)kk * ldbk]);
        }
    }

    float acc[2][4][4] = {};
    for (int k0 = 0; k0 < K; k0 += 16) {
        *(uint4*)(&As[(ar     )*20 + ac]) = ua0;
        *(uint4*)(&As[(ar + 64)*20 + ac]) = ua1;
        if (bvec) {
            *(uint4*)(&Bs[ar*20 + ac]) = ub;
        } else {
            #pragma unroll
            for (int p = 0; p < 4; p++) {
                int idx = t + 256*p; int nn = idx & 63, kk = idx >> 6;
                Bs[nn*20 + kk] = ubs[p];
            }
        }
        __syncthreads();
        if (k0 + 16 < K) {
            const float* An = Abase + k0 + 16;
            ua0 = cvt4(*(const float4*)(An));
            ua1 = cvt4(*(const float4*)(An + (long)64 * lda));
            if (bvec) {
                ub = cvt4(*(const float4*)(B + (long)(n0 + ar) * ldbn + k0 + 16 + ac));
            } else {
                #pragma unroll
                for (int p = 0; p < 4; p++) {
                    int idx = t + 256*p; int nn = idx & 63, kk = idx >> 6;
                    ubs[p] = f2tf(B[(long)(n0 + nn) + (long)(k0 + 16 + kk) * ldbk]);
                }
            }
        }
        #pragma unroll
        for (int ks = 0; ks < 2; ks++) {
            int kk = ks * 8;
            uint32_t af[2][4];
            #pragma unroll
            for (int ms = 0; ms < 2; ms++) {
                int mr = wm*32 + ms*16 + g;
                af[ms][0] = As[(mr    )*20 + kk + q];
                af[ms][1] = As[(mr + 8)*20 + kk + q];
                af[ms][2] = As[(mr    )*20 + kk + q + 4];
                af[ms][3] = As[(mr + 8)*20 + kk + q + 4];
            }
            uint32_t bf[4][2];
            #pragma unroll
            for (int ns = 0; ns < 4; ns++) {
                int nc = wn*32 + ns*8 + g;
                bf[ns][0] = Bs[nc*20 + kk + q];
                bf[ns][1] = Bs[nc*20 + kk + q + 4];
            }
            #pragma unroll
            for (int ms = 0; ms < 2; ms++)
                #pragma unroll
                for (int ns = 0; ns < 4; ns++)
                    mma_tf32(acc[ms][ns][0], acc[ms][ns][1], acc[ms][ns][2], acc[ms][ns][3],
                             af[ms][0], af[ms][1], af[ms][2], af[ms][3],
                             bf[ns][0], bf[ns][1]);
        }
        __syncthreads();
    }
    #pragma unroll
    for (int ms = 0; ms < 2; ms++)
        #pragma unroll
        for (int ns = 0; ns < 4; ns++) {
            int row0 = m0 + wm*32 + ms*16 + g;
            int col  = n0 + wn*32 + ns*8 + 2*q;
            float bx0 = 0.f, bx1 = 0.f;
            if (bias) { bx0 = bias[col]; bx1 = bias[col+1]; }
            *(float2*)(&Cp[(long)row0*ldc + col]) =
                make_float2(acc[ms][ns][0] + bx0, acc[ms][ns][1] + bx1);
            *(float2*)(&Cp[(long)(row0+8)*ldc + col]) =
                make_float2(acc[ms][ns][2] + bx0, acc[ms][ns][3] + bx1);
        }
}

// ---------------- 4) fused attention, 256 threads, occupancy 2 (unchanged) ----------------
#define SKS 268
#define SQS 516
#define OFF_SQ   17152
#define OFF_RED  21280
#define OFF_SC   25376
#define OFF_SA   25888
#define OFF_SMAX 26400
#define OFF_SRS  26408
#define OFF_RXY  26416
#define OFF_W1E  26544
#define OFF_W1O  26800
#define OFF_B1S  27056
#define ATTN_FLTS 27312
#define ATTN_SMEM (ATTN_FLTS*4)

__global__ __launch_bounds__(256, 2)
void attn_kernel(const float* __restrict__ qk, const float* __restrict__ key2,
                 const float* __restrict__ r, const float* __restrict__ w1,
                 const float* __restrict__ b1, float* __restrict__ ctx) {
    extern __shared__ float smf[];
    float* skey = smf;
    float* sq   = smf + OFF_SQ;
    float* red  = smf + OFF_RED;
    float* sc   = smf + OFF_SC;
    float* sa   = smf + OFF_SA;
    float* smax = smf + OFF_SMAX;
    float* srs  = smf + OFF_SRS;
    float* rxy  = smf + OFF_RXY;
    float* w1e  = smf + OFF_W1E;
    float* w1o  = smf + OFF_W1O;
    float* b1s  = smf + OFF_B1S;

    int b = blockIdx.x, t = threadIdx.x;

    const float* keyb = key2 + (long)b * (64*256);
    #pragma unroll
    for (int q = 0; q < 16; q++) {
        int idx = t + 256*q;
        int row = idx >> 6, c4 = (idx & 63) * 4;
        *(float4*)(skey + row*SKS + c4) = *(const float4*)(keyb + row*256 + c4);
    }
    {
        const float4* qsrc = (const float4*)(qk + (long)b * 4096);
        #pragma unroll
        for (int q = 0; q < 4; q++) {
            int idx = t + 256*q;
            int row = idx >> 7, c = idx & 127;
            *(float4*)(sq + row*SQS + c*4) = qsrc[row*128 + c];
        }
    }
    if (t < 128) rxy[t] = r[b*128 + t];
    w1e[t] = w1[2*t]; w1o[t] = w1[2*t+1]; b1s[t] = b1[t];
    __syncthreads();

    // ---- phase 1: scores ----
    {
        int s = t >> 5, lane = t & 31;
        int hq = lane >> 4, kq = lane & 15;
        int h0 = hq * 4, jb = s * 32;
        u64 acc2[4][4] = {};
        #pragma unroll
        for (int st = 0; st < 8; st++) {
            int jj = jb + st*4;
            ulonglong2 a0 = *(const ulonglong2*)(sq + (h0+0)*SQS + jj);
            ulonglong2 a1 = *(const ulonglong2*)(sq + (h0+1)*SQS + jj);
            ulonglong2 a2 = *(const ulonglong2*)(sq + (h0+2)*SQS + jj);
            ulonglong2 a3 = *(const ulonglong2*)(sq + (h0+3)*SQS + jj);
            #pragma unroll
            for (int m = 0; m < 4; m++) {
                ulonglong2 bv = *(const ulonglong2*)(skey + (kq + 16*m)*SKS + jj);
                acc2[0][m] = fma2(a0.x, bv.x, acc2[0][m]); acc2[0][m] = fma2(a0.y, bv.y, acc2[0][m]);
                acc2[1][m] = fma2(a1.x, bv.x, acc2[1][m]); acc2[1][m] = fma2(a1.y, bv.y, acc2[1][m]);
                acc2[2][m] = fma2(a2.x, bv.x, acc2[2][m]); acc2[2][m] = fma2(a2.y, bv.y, acc2[2][m]);
                acc2[3][m] = fma2(a3.x, bv.x, acc2[3][m]); acc2[3][m] = fma2(a3.y, bv.y, acc2[3][m]);
            }
        }
        u64 xs[4], ys[4];
        #pragma unroll
        for (int m = 0; m < 4; m++) {
            int k = kq + 16*m;
            xs[m] = splat2(rxy[2*k]);
            ys[m] = splat2(rxy[2*k+1]);
        }
        #pragma unroll
        for (int st = 0; st < 8; st++) {
            int w = jb + st*4, jj = 256 + w;
            ulonglong2 a0 = *(const ulonglong2*)(sq + (h0+0)*SQS + jj);
            ulonglong2 a1 = *(const ulonglong2*)(sq + (h0+1)*SQS + jj);
            ulonglong2 a2 = *(const ulonglong2*)(sq + (h0+2)*SQS + jj);
            ulonglong2 a3 = *(const ulonglong2*)(sq + (h0+3)*SQS + jj);
            ulonglong2 we2 = *(const ulonglong2*)(w1e + w);
            ulonglong2 wo2 = *(const ulonglong2*)(w1o + w);
            ulonglong2 bc2 = *(const ulonglong2*)(b1s + w);
            #pragma unroll
            for (int m = 0; m < 4; m++) {
                u64 bv01 = fma2(xs[m], we2.x, fma2(ys[m], wo2.x, bc2.x));
                u64 bv23 = fma2(xs[m], we2.y, fma2(ys[m], wo2.y, bc2.y));
                acc2[0][m] = fma2(a0.x, bv01, acc2[0][m]); acc2[0][m] = fma2(a0.y, bv23, acc2[0][m]);
                acc2[1][m] = fma2(a1.x, bv01, acc2[1][m]); acc2[1][m] = fma2(a1.y, bv23, acc2[1][m]);
                acc2[2][m] = fma2(a2.x, bv01, acc2[2][m]); acc2[2][m] = fma2(a2.y, bv23, acc2[2][m]);
                acc2[3][m] = fma2(a3.x, bv01, acc2[3][m]); acc2[3][m] = fma2(a3.y, bv23, acc2[3][m]);
            }
        }
        #pragma unroll
        for (int hi = 0; hi < 4; hi++)
            #pragma unroll
            for (int m = 0; m < 4; m++) {
                float2 u = unpack2(acc2[hi][m]);
                red[s*512 + (h0+hi)*64 + m*16 + kq] = u.x + u.y;
            }
    }
    __syncthreads();
    #pragma unroll
    for (int e0 = 0; e0 < 2; e0++) {
        int e = t + e0*256;
        float v = 0.f;
        #pragma unroll
        for (int s2 = 0; s2 < 8; s2++) v += red[s2*512 + e];
        sc[e] = v * 0.125f;
    }
    __syncthreads();

    if (t < 32) {
        int h = t >> 2, seg = t & 3;
        const float* p = sc + h*64 + seg*16;
        float mx = p[0];
        #pragma unroll
        for (int i = 1; i < 16; i++) mx = fmaxf(mx, p[i]);
        mx = fmaxf(mx, __shfl_xor_sync(0xffffffffu, mx, 1));
        mx = fmaxf(mx, __shfl_xor_sync(0xffffffffu, mx, 2));
        float sm = 0.f;
        #pragma unroll
        for (int i = 0; i < 16; i++) sm += __expf(p[i] - mx);
        sm += __shfl_xor_sync(0xffffffffu, sm, 1);
        sm += __shfl_xor_sync(0xffffffffu, sm, 2);
        if (seg == 0) { smax[h] = mx; srs[h] = 1.0f / sm; }
    }
    __syncthreads();
    sa[t]     = __expf(sc[t]     - smax[t >> 6])        * srs[t >> 6];
    sa[t+256] = __expf(sc[t+256] - smax[(t+256) >> 6])  * srs[(t+256) >> 6];
    __syncthreads();

    {
        int hq = t >> 7, jq = t & 127;
        int h0 = hq * 4, j0 = jq * 4;
        const float* sa0 = sa + (h0+0)*64;
        const float* sa1 = sa + (h0+1)*64;
        const float* sa2 = sa + (h0+2)*64;
        const float* sa3 = sa + (h0+3)*64;
        u64 acc2[4][2] = {};
        if (j0 < 256) {
            #pragma unroll
            for (int k4 = 0; k4 < 64; k4 += 4) {
                float4 av0 = *(const float4*)(sa0 + k4);
                float4 av1 = *(const float4*)(sa1 + k4);
                float4 av2 = *(const float4*)(sa2 + k4);
                float4 av3 = *(const float4*)(sa3 + k4);
                float a0r[4] = {av0.x, av0.y, av0.z, av0.w};
                float a1r[4] = {av1.x, av1.y, av1.z, av1.w};
                float a2r[4] = {av2.x, av2.y, av2.z, av2.w};
                float a3r[4] = {av3.x, av3.y, av3.z, av3.w};
                #pragma unroll
                for (int kk = 0; kk < 4; kk++) {
                    ulonglong2 bv = *(const ulonglong2*)(skey + (k4+kk)*SKS + j0);
                    u64 s0 = splat2(a0r[kk]), s1 = splat2(a1r[kk]);
                    u64 s2 = splat2(a2r[kk]), s3 = splat2(a3r[kk]);
                    acc2[0][0]=fma2(s0,bv.x,acc2[0][0]); acc2[0][1]=fma2(s0,bv.y,acc2[0][1]);
                    acc2[1][0]=fma2(s1,bv.x,acc2[1][0]); acc2[1][1]=fma2(s1,bv.y,acc2[1][1]);
                    acc2[2][0]=fma2(s2,bv.x,acc2[2][0]); acc2[2][1]=fma2(s2,bv.y,acc2[2][1]);
                    acc2[3][0]=fma2(s3,bv.x,acc2[3][0]); acc2[3][1]=fma2(s3,bv.y,acc2[3][1]);
                }
            }
        } else {
            int w = j0 - 256;
            ulonglong2 we2 = *(const ulonglong2*)(w1e + w);
            ulonglong2 wo2 = *(const ulonglong2*)(w1o + w);
            ulonglong2 bc2 = *(const ulonglong2*)(b1s + w);
            #pragma unroll
            for (int k4 = 0; k4 < 64; k4 += 4) {
                float4 av0 = *(const float4*)(sa0 + k4);
                float4 av1 = *(const float4*)(sa1 + k4);
                float4 av2 = *(const float4*)(sa2 + k4);
                float4 av3 = *(const float4*)(sa3 + k4);
                float a0r[4] = {av0.x, av0.y, av0.z, av0.w};
                float a1r[4] = {av1.x, av1.y, av1.z, av1.w};
                float a2r[4] = {av2.x, av2.y, av2.z, av2.w};
                float a3r[4] = {av3.x, av3.y, av3.z, av3.w};
                #pragma unroll
                for (int kk = 0; kk < 4; kk++) {
                    int k = k4 + kk;
                    u64 xs = splat2(rxy[2*k]), ys = splat2(rxy[2*k+1]);
                    u64 bv01 = fma2(xs, we2.x, fma2(ys, wo2.x, bc2.x));
                    u64 bv23 = fma2(xs, we2.y, fma2(ys, wo2.y, bc2.y));
                    u64 s0 = splat2(a0r[kk]), s1 = splat2(a1r[kk]);
                    u64 s2 = splat2(a2r[kk]), s3 = splat2(a3r[kk]);
                    acc2[0][0]=fma2(s0,bv01,acc2[0][0]); acc2[0][1]=fma2(s0,bv23,acc2[0][1]);
                    acc2[1][0]=fma2(s1,bv01,acc2[1][0]); acc2[1][1]=fma2(s1,bv23,acc2[1][1]);
                    acc2[2][0]=fma2(s2,bv01,acc2[2][0]); acc2[2][1]=fma2(s2,bv23,acc2[2][1]);
                    acc2[3][0]=fma2(s3,bv01,acc2[3][0]); acc2[3][1]=fma2(s3,bv23,acc2[3][1]);
                }
            }
        }
        float* ctxb = ctx + (long)b * 4096;
        #pragma unroll
        for (int hi = 0; hi < 4; hi++) {
            float2 u0 = unpack2(acc2[hi][0]);
            float2 u1 = unpack2(acc2[hi][1]);
            float4 o = make_float4(u0.x, u0.y, u1.x, u1.y);
            *(float4*)(ctxb + (h0+hi)*512 + j0) = o;
        }
    }
}

// ---------------- host launcher ----------------
extern "C" void kernel_launch(void* const* d_in, const int* in_sizes, int n_in,
                              void* d_out, int out_size) {
    const float* Z          = (const float*)d_in[0];
    const float* Q          = (const float*)d_in[1];
    const float* q_z        = (const float*)d_in[2];
    const float* r          = (const float*)d_in[3];
    const float* w1         = (const float*)d_in[4];
    const float* b1         = (const float*)d_in[5];
    const float* w2         = (const float*)d_in[6];
    const float* b2         = (const float*)d_in[7];
    const float* in_proj_w  = (const float*)d_in[8];
    const float* in_proj_b  = (const float*)d_in[9];
    const float* out_proj_w = (const float*)d_in[10];
    const float* out_proj_b = (const float*)d_in[11];
    float* outp = (float*)d_out;

    float *pKey2, *pQl, *pQk, *pCtx, *pOut1;
    cudaGetSymbolAddress((void**)&pKey2,  g_key2);
    cudaGetSymbolAddress((void**)&pQl,    g_ql);
    cudaGetSymbolAddress((void**)&pQk,    g_qk);
    cudaGetSymbolAddress((void**)&pCtx,   g_ctx);
    cudaGetSymbolAddress((void**)&pOut1,  g_out1);

    cudaFuncSetAttribute(attn_kernel,
                         cudaFuncAttributeMaxDynamicSharedMemorySize, ATTN_SMEM);

    // 1) transpose Z -> Zt
    transpose_kernel<<<dim3((HWn*HWn)/32, Cn/32), dim3(32, 8)>>>(Z);

    // 2) fat kernel: gemm1(fused query, tf32) + qz->out copy + interp
    fat_kernel<<<FAT_INTERP_OFF + NPn/32, 256>>>(
        r, q_z, Q, w2, b2, in_proj_w, in_proj_b, outp);

    // 3) qk[b][h][n] = sum_d ql[b][h*64+d] * Wk[h*64+d][n]
    gemm_kernel<<<dim3(En/64, SQn/128, NHn), 256>>>(
        pQl, En, (long)HDn,
        in_proj_w + (long)En*En, 1, En, (long)HDn*En,
        pQk, NHn*En, (long)En,
        (const float*)0, 0L,
        SQn, En, HDn);

    // 4) fused attention
    attn_kernel<<<SQn, 256, ATTN_SMEM>>>(pQk, pKey2, r, w1, b1, pCtx);

    // 5) out1[b][h*64+d] = ctx[b][h][:] . Wv[h*64+d][:] + bv
    gemm_kernel<<<dim3(HDn/64, SQn/128, NHn), 256>>>(
        pCtx, NHn*En, (long)En,
        in_proj_w + (long)2*En*En, En, 1, (long)HDn*En,
        pOut1, En, (long)HDn,
        in_proj_b + (long)2*En, (long)HDn,
        SQn, HDn, En);

    // 6) final out_proj into d_out cols [256,768)
    gemm_kernel<<<dim3(En/64, SQn/128, 1), 256>>>(
        pOut1, En, 0L,
        out_proj_w, En, 1, 0L,
        outp + 256, 768, 0L,
        out_proj_b, 0L,
        SQn, En, En);
}